// round 16
// baseline (speedup 1.0000x reference)
#include <cuda_runtime.h>
#include <cuda_fp16.h>
#include <cstdint>

// Problem constants
#define NB   4
#define SEQ  2048
#define DIM  1024
#define MTOT (NB * SEQ)   // 8192

// GEMM tiling (fp16 operands), 2 CTAs/SM, persistent grid
#define BM 128
#define BN 128
#define BK 64                            // 64 halves = 128 B per row slab
#define ASTAGE (BM * BK * 2)             // 16384 B
#define BSTAGE (BN * BK * 2)             // 16384 B
#define STAGEB (ASTAGE + BSTAGE)         // 32768 B
#define GEMM_SMEM (3 * STAGEB)           // 98304 B (3 stages; covers 128*129*4 staging)
#define NPERS 296                        // 2 CTAs x 148 SMs

// Epilogue modes
#define MODE_PLAIN 0   // C = alpha*acc + bias            (outHalf ? half : float)
#define MODE_EXP   1   // C = h(exp(alpha*acc)); aux = partial row sums [rows][64]
#define MODE_NORM  2   // C = h(acc * aux[row])           (aux = inv row sums)
#define MODE_QKV   4   // fused QKV: seg 0 -> Q plain, seg 1 -> K plain, seg 2 -> Vt transposed

// ---------------- scratch (__device__ globals; no allocation allowed) ------
__device__ __half g_X [(size_t)MTOT * DIM];
__device__ __half g_Q [(size_t)MTOT * DIM];
__device__ __half g_K [(size_t)MTOT * DIM];
__device__ __half g_Vt[(size_t)MTOT * DIM];
__device__ __half g_P [(size_t)NB * SEQ * SEQ];
__device__ __half g_C [(size_t)MTOT * DIM];
__device__ __half g_Wt[(size_t)4 * DIM * DIM];
__device__ float  g_ps[(size_t)MTOT * 64];
__device__ float  g_inv[(size_t)MTOT];
__device__ unsigned int g_ctr[4];        // dynamic tile counters (reset each call)

// ---------------- helpers ---------------------------------------------------
__device__ __forceinline__ uint32_t smem_u32(const void* p) {
    uint32_t a;
    asm("{ .reg .u64 t; cvta.to.shared.u64 t, %1; cvt.u32.u64 %0, t; }" : "=r"(a) : "l"(p));
    return a;
}

__device__ __forceinline__ uint32_t h2pack(float a, float b) {
    __half2 h = __floats2half2_rn(a, b);
    return *(uint32_t*)&h;
}

#define CP_ASYNC16(dst, src) \
    asm volatile("cp.async.cg.shared.global [%0], [%1], 16;" :: "r"(dst), "l"(src) : "memory")
#define CP_COMMIT() asm volatile("cp.async.commit_group;" ::: "memory")
#define CP_WAIT1()  asm volatile("cp.async.wait_group 1;" ::: "memory")

__device__ __forceinline__ void ldsm4(uint32_t* r, uint32_t addr) {
    asm volatile("ldmatrix.sync.aligned.m8n8.x4.shared.b16 {%0,%1,%2,%3}, [%4];"
                 : "=r"(r[0]), "=r"(r[1]), "=r"(r[2]), "=r"(r[3]) : "r"(addr));
}

// m16n8k16 fp16, fp32 accumulate
__device__ __forceinline__ void mma16(float* c, const uint32_t* a, const uint32_t* b) {
    asm volatile(
        "mma.sync.aligned.m16n8k16.row.col.f32.f16.f16.f32 "
        "{%0,%1,%2,%3}, {%4,%5,%6,%7}, {%8,%9}, {%0,%1,%2,%3};"
        : "+f"(c[0]), "+f"(c[1]), "+f"(c[2]), "+f"(c[3])
        : "r"(a[0]), "r"(a[1]), "r"(a[2]), "r"(a[3]),
          "r"(b[0]), "r"(b[1]));
}

// ---------------- persistent NT GEMM (mma.sync fp16 + ldmatrix + cp.async) --
// acc[M,N] = A[M,K] * B[N,K]^T per tile; epilogue per mode.
// A, B K-major fp16. Tiles of 128x128; grid = NPERS persistent CTAs; each CTA
// pops tiles from ctr until numTiles exhausted (output deterministic: tile ->
// output mapping is fixed). 256 threads, 8 warps (2m x 4n), warp tile 64x32,
// 3-stage cp.async, 2 CTAs/SM.
__global__ __launch_bounds__(256, 2)
void gemm_nt_mma(const __half* __restrict__ A0, const __half* __restrict__ B0,
                 const float* __restrict__ bias, void* __restrict__ Cv,
                 int N, int K, float alpha, int mode, int outHalf,
                 float* __restrict__ aux,
                 const float* __restrict__ bias2, const float* __restrict__ bias3,
                 void* __restrict__ Cv2, void* __restrict__ Cv3,
                 size_t strA, size_t strB, size_t strC,
                 unsigned int* __restrict__ ctr, int numTiles, int gx, int gy)
{
    extern __shared__ char smem[];
    const uint32_t sbase = smem_u32(smem);
    __shared__ unsigned int s_tile;

    const int tid  = threadIdx.x;
    const int lane = tid & 31;
    const int wid  = tid >> 5;
    const int wm   = wid & 1;          // 2 warps along M (64 rows each)
    const int wn   = wid >> 1;         // 4 warps along N (32 cols each)

    // ldmatrix octet mapping (same for A and B)
    const int lrow = (lane & 7) + ((lane >> 3) & 1) * 8;
    const int lcol = ((lane >> 4) & 1) * 16;
    const uint32_t xmask = (uint32_t)((lane & 7) << 4);   // swizzle XOR (row&7)
    const int lr = tid >> 3;           // loader row 0..31
    const int lc = tid & 7;            // loader 16B chunk

    uint32_t abase[4], bbase[2];
#pragma unroll
    for (int mi = 0; mi < 4; mi++)
        abase[mi] = (uint32_t)((wm * 64 + mi * 16 + lrow) * 128 + lcol);
#pragma unroll
    for (int q = 0; q < 2; q++)
        bbase[q] = (uint32_t)((wn * 32 + q * 16 + lrow) * 128 + lcol);

    const int g  = lane >> 2;
    const int tg = lane & 3;

    for (;;) {
        if (tid == 0) s_tile = atomicAdd(ctr, 1u);
        __syncthreads();
        const unsigned int t = s_tile;
        if ((int)t >= numTiles) return;
        __syncthreads();                 // s_tile consumed; smem free for staging

        const int bx = (int)(t % (unsigned)gx);
        const int by = (int)((t / (unsigned)gx) % (unsigned)gy);
        const int bz = (int)(t / (unsigned)(gx * gy));
        const int m0 = by * BM;
        const int n0 = bx * BN;

        const __half* A = A0 + (size_t)bz * strA;
        const __half* B = B0 + (size_t)bz * strB;
        __half* Ch = (__half*)Cv + (size_t)bz * strC;
        float*  Cf = (float*)Cv  + (size_t)bz * strC;

        float acc[4][4][4];
#pragma unroll
        for (int i = 0; i < 4; i++)
#pragma unroll
            for (int j = 0; j < 4; j++)
#pragma unroll
                for (int r = 0; r < 4; r++) acc[i][j][r] = 0.f;

        auto loadStage = [&](int i, int s) {
            const uint32_t baseA = sbase + (uint32_t)s * STAGEB;
            const uint32_t baseB = baseA + ASTAGE;
            const __half* Ag = A + (size_t)m0 * K + (size_t)i * BK + lc * 8;
            const __half* Bg = B + (size_t)n0 * K + (size_t)i * BK + lc * 8;
#pragma unroll
            for (int p = 0; p < 4; p++) {
                const int r = p * 32 + lr;
                CP_ASYNC16(baseA + (uint32_t)(r * 128 + ((lc ^ (r & 7)) * 16)),
                           (const void*)(Ag + (size_t)r * K));
            }
#pragma unroll
            for (int p = 0; p < 4; p++) {
                const int r = p * 32 + lr;
                CP_ASYNC16(baseB + (uint32_t)(r * 128 + ((lc ^ (r & 7)) * 16)),
                           (const void*)(Bg + (size_t)r * K));
            }
        };

        const int nIter = K / BK;
        loadStage(0, 0); CP_COMMIT();
        loadStage(1, 1); CP_COMMIT();

        int s = 0;
        for (int i = 0; i < nIter; i++) {
            CP_WAIT1();
            __syncthreads();

            const uint32_t aS = sbase + (uint32_t)s * STAGEB;
            const uint32_t bS = aS + ASTAGE;
#pragma unroll
            for (int kk = 0; kk < 4; kk++) {
                uint32_t a[4][4];
                uint32_t b[4][2];
#pragma unroll
                for (int mi = 0; mi < 4; mi++)
                    ldsm4(a[mi], aS + ((abase[mi] + kk * 32) ^ xmask));
#pragma unroll
                for (int q = 0; q < 2; q++) {
                    uint32_t r[4];
                    ldsm4(r, bS + ((bbase[q] + kk * 32) ^ xmask));
                    b[2 * q][0]     = r[0]; b[2 * q][1]     = r[2];
                    b[2 * q + 1][0] = r[1]; b[2 * q + 1][1] = r[3];
                }
#pragma unroll
                for (int mi = 0; mi < 4; mi++)
#pragma unroll
                    for (int ni = 0; ni < 4; ni++)
                        mma16(acc[mi][ni], a[mi], b[ni]);
            }

            if (i + 2 < nIter) {
                int s2 = s + 2; if (s2 >= 3) s2 -= 3;
                loadStage(i + 2, s2);
            }
            CP_COMMIT();
            s++; if (s == 3) s = 0;
        }

        // ---- epilogues ----
        const int growBase = bz * (gy * BM) + m0 + wm * 64;

        if (mode == MODE_QKV) {
            const int seg = n0 >> 10;          // 0:Q  1:K  2:Vt
            if (seg < 2) {
                __half* dstb = (seg == 0) ? Ch : (__half*)Cv2;
                const float* bb = (seg == 0) ? bias : bias2;
#pragma unroll
                for (int mi = 0; mi < 4; mi++) {
                    const int mrow = m0 + wm * 64 + mi * 16 + g;
#pragma unroll
                    for (int ni = 0; ni < 4; ni++) {
                        const int nc  = n0 + wn * 32 + ni * 8 + 2 * tg;
                        const int ncl = nc & 1023;
                        float b0 = __ldg(bb + ncl), b1 = __ldg(bb + ncl + 1);
                        *(uint32_t*)&dstb[(size_t)mrow * DIM + ncl] =
                            h2pack(acc[mi][ni][0] + b0, acc[mi][ni][1] + b1);
                        *(uint32_t*)&dstb[(size_t)(mrow + 8) * DIM + ncl] =
                            h2pack(acc[mi][ni][2] + b0, acc[mi][ni][3] + b1);
                    }
                }
            } else {
                __syncthreads();
                float* sf = (float*)smem;
#pragma unroll
                for (int mi = 0; mi < 4; mi++) {
                    const int mr = wm * 64 + mi * 16 + g;
#pragma unroll
                    for (int ni = 0; ni < 4; ni++) {
                        const int ncl = wn * 32 + ni * 8 + 2 * tg;
                        const int nbi = (n0 & 1023) + ncl;
                        float b0 = __ldg(bias3 + nbi), b1 = __ldg(bias3 + nbi + 1);
                        sf[(ncl)     * 129 + mr]     = acc[mi][ni][0] + b0;
                        sf[(ncl + 1) * 129 + mr]     = acc[mi][ni][1] + b1;
                        sf[(ncl)     * 129 + mr + 8] = acc[mi][ni][2] + b0;
                        sf[(ncl + 1) * 129 + mr + 8] = acc[mi][ni][3] + b1;
                    }
                }
                __syncthreads();
                const int b  = m0 >> 11;
                const int s0 = m0 & 2047;
                const int col = tid & 127;
                const int rh  = (tid >> 7) * 64;
                __half* dst = (__half*)Cv3 + (size_t)b * DIM * SEQ
                            + (size_t)((n0 & 1023) + col) * SEQ + s0 + rh;
                const float* src = sf + (size_t)col * 129 + rh;
#pragma unroll
                for (int m4 = 0; m4 < 64; m4 += 4) {
                    uint2 v;
                    v.x = h2pack(src[m4],     src[m4 + 1]);
                    v.y = h2pack(src[m4 + 2], src[m4 + 3]);
                    *(uint2*)(dst + m4) = v;
                }
            }
        } else if (mode == MODE_EXP) {
            float rs[4][2];
#pragma unroll
            for (int mi = 0; mi < 4; mi++) { rs[mi][0] = 0.f; rs[mi][1] = 0.f; }
#pragma unroll
            for (int mi = 0; mi < 4; mi++) {
                const int mrow = m0 + wm * 64 + mi * 16 + g;
#pragma unroll
                for (int ni = 0; ni < 4; ni++) {
                    const int nc = n0 + wn * 32 + ni * 8 + 2 * tg;
                    __half2 h0 = __floats2half2_rn(__expf(acc[mi][ni][0] * alpha),
                                                   __expf(acc[mi][ni][1] * alpha));
                    __half2 h1 = __floats2half2_rn(__expf(acc[mi][ni][2] * alpha),
                                                   __expf(acc[mi][ni][3] * alpha));
                    float2 f0 = __half22float2(h0);
                    float2 f1 = __half22float2(h1);
                    rs[mi][0] += f0.x + f0.y;
                    rs[mi][1] += f1.x + f1.y;
                    *(__half2*)&Ch[(size_t)mrow * N + nc]       = h0;
                    *(__half2*)&Ch[(size_t)(mrow + 8) * N + nc] = h1;
                }
            }
            const int slot = bx * 4 + wn;    // gx = 16 -> slots 0..63
#pragma unroll
            for (int mi = 0; mi < 4; mi++) {
#pragma unroll
                for (int h = 0; h < 2; h++) {
                    float v = rs[mi][h];
                    v += __shfl_xor_sync(0xffffffffu, v, 1);
                    v += __shfl_xor_sync(0xffffffffu, v, 2);
                    if (tg == 0) {
                        const int grow = growBase + mi * 16 + g + h * 8;
                        aux[(size_t)grow * 64 + slot] = v;
                    }
                }
            }
        } else {
            // MODE_PLAIN / MODE_NORM
#pragma unroll
            for (int mi = 0; mi < 4; mi++) {
                const int mrow = m0 + wm * 64 + mi * 16 + g;
                float inv0 = 1.f, inv1 = 1.f;
                if (mode == MODE_NORM) {
                    const int grow = growBase + mi * 16 + g;
                    inv0 = __ldg(aux + grow);
                    inv1 = __ldg(aux + grow + 8);
                }
#pragma unroll
                for (int ni = 0; ni < 4; ni++) {
                    const int nc = n0 + wn * 32 + ni * 8 + 2 * tg;
                    float b0 = 0.f, b1 = 0.f;
                    if (bias) { b0 = __ldg(bias + nc); b1 = __ldg(bias + nc + 1); }
                    float2 r0, r1;
                    if (mode == MODE_NORM) {
                        r0 = make_float2(acc[mi][ni][0] * inv0, acc[mi][ni][1] * inv0);
                        r1 = make_float2(acc[mi][ni][2] * inv1, acc[mi][ni][3] * inv1);
                    } else {
                        r0 = make_float2(acc[mi][ni][0] * alpha + b0, acc[mi][ni][1] * alpha + b1);
                        r1 = make_float2(acc[mi][ni][2] * alpha + b0, acc[mi][ni][3] * alpha + b1);
                    }
                    if (outHalf) {
                        *(uint32_t*)&Ch[(size_t)mrow * N + nc]       = h2pack(r0.x, r0.y);
                        *(uint32_t*)&Ch[(size_t)(mrow + 8) * N + nc] = h2pack(r1.x, r1.y);
                    } else {
                        *(float2*)&Cf[(size_t)mrow * N + nc]       = r0;
                        *(float2*)&Cf[(size_t)(mrow + 8) * N + nc] = r1;
                    }
                }
            }
        }
        __syncthreads();   // smem (staging) free before next tile's loads
    }
}

// ---------------- aux kernels ----------------------------------------------

// zero the dynamic tile counters (must run before GEMMs each replay)
__global__ void reset_ctrs()
{
    if (threadIdx.x < 4) g_ctr[threadIdx.x] = 0u;
}

// fp32 -> fp16 copy (prepares x for the projection GEMMs)
__global__ __launch_bounds__(256)
void half_copy4(const float4* __restrict__ in, uint2* __restrict__ out, int n4)
{
    int i = blockIdx.x * 256 + threadIdx.x;
    if (i < n4) {
        float4 v = in[i];
        uint2 o;
        o.x = h2pack(v.x, v.y);
        o.y = h2pack(v.z, v.w);
        out[i] = o;
    }
}

// all 4 weight transposes in one launch: out[z][C,R] = half(W_z[R,C]^T)
__global__ __launch_bounds__(256)
void transpose4w(const float* __restrict__ W0, const float* __restrict__ W1,
                 const float* __restrict__ W2, const float* __restrict__ W3,
                 __half* __restrict__ out)
{
    __shared__ float t[32][33];
    const float* in = (blockIdx.z == 0) ? W0 : (blockIdx.z == 1) ? W1
                    : (blockIdx.z == 2) ? W2 : W3;
    __half* dst = out + (size_t)blockIdx.z * DIM * DIM;
    const int x  = blockIdx.x * 32 + threadIdx.x;
    const int y0 = blockIdx.y * 32;
#pragma unroll
    for (int j = threadIdx.y; j < 32; j += 8)
        t[j][threadIdx.x] = in[(size_t)(y0 + j) * DIM + x];
    __syncthreads();
    const int ox  = y0 + threadIdx.x;
    const int oy0 = blockIdx.x * 32;
#pragma unroll
    for (int j = threadIdx.y; j < 32; j += 8)
        dst[(size_t)(oy0 + j) * DIM + ox] = __float2half_rn(t[threadIdx.x][j]);
}

// inv[r] = 1 / sum(partial[r][0..63])
__global__ __launch_bounds__(256)
void rowsum_inv(const float* __restrict__ partial, float* __restrict__ inv, int rows)
{
    int r = blockIdx.x * 256 + threadIdx.x;
    if (r < rows) {
        const float4* p = (const float4*)(partial + (size_t)r * 64);
        float s = 0.f;
#pragma unroll
        for (int i = 0; i < 16; i++) {
            float4 v = p[i];
            s += (v.x + v.y) + (v.z + v.w);
        }
        inv[r] = 1.0f / s;
    }
}

// ---------------- launch ----------------------------------------------------
extern "C" void kernel_launch(void* const* d_in, const int* in_sizes, int n_in,
                              void* d_out, int out_size)
{
    const float* x  = (const float*)d_in[0];
    const float* Wq = (const float*)d_in[1];
    const float* bq = (const float*)d_in[2];
    const float* Wk = (const float*)d_in[3];
    const float* bk = (const float*)d_in[4];
    const float* Wv = (const float*)d_in[5];
    const float* bv = (const float*)d_in[6];
    const float* Wo = (const float*)d_in[7];
    const float* bo = (const float*)d_in[8];
    float* out = (float*)d_out;

    __half *X, *Q, *K, *Vt, *P, *C, *Wt;
    float *PS, *INV;
    unsigned int* CTR;
    cudaGetSymbolAddress((void**)&X,   g_X);
    cudaGetSymbolAddress((void**)&Q,   g_Q);
    cudaGetSymbolAddress((void**)&K,   g_K);
    cudaGetSymbolAddress((void**)&Vt,  g_Vt);
    cudaGetSymbolAddress((void**)&P,   g_P);
    cudaGetSymbolAddress((void**)&C,   g_C);
    cudaGetSymbolAddress((void**)&Wt,  g_Wt);
    cudaGetSymbolAddress((void**)&PS,  g_ps);
    cudaGetSymbolAddress((void**)&INV, g_inv);
    cudaGetSymbolAddress((void**)&CTR, g_ctr);

    cudaFuncSetAttribute(gemm_nt_mma, cudaFuncAttributeMaxDynamicSharedMemorySize, GEMM_SMEM);

    const float scale = 1.0f / 32.0f;   // 1/sqrt(1024)

    // 0) reset tile counters (graph replays must be idempotent)
    reset_ctrs<<<1, 4>>>();

    // 1) fp16 x
    half_copy4<<<(MTOT * DIM / 4 + 255) / 256, 256>>>((const float4*)x, (uint2*)X, MTOT * DIM / 4);

    // 2) all weight transposes (one launch); Wt = [Wq^T | Wk^T | Wv^T | Wo^T]
    transpose4w<<<dim3(DIM / 32, DIM / 32, 4), dim3(32, 8)>>>(Wq, Wk, Wv, Wo, Wt);

    // 3) fused QKV projection: tiles 24 x 64 (seg0 Q, seg1 K, seg2 Vt)
    gemm_nt_mma<<<NPERS, 256, GEMM_SMEM>>>(X, Wt, bq, Q,
                                           DIM, DIM, 1.f, MODE_QKV, 1, nullptr,
                                           bk, bv, K, Vt, 0, 0, 0,
                                           CTR + 0, 24 * 64, 24, 64);

    // 4) expP = exp(scale * Q K^T) (half), partial row sums; tiles 16 x 16 x 4
    gemm_nt_mma<<<NPERS, 256, GEMM_SMEM>>>(Q, K, nullptr, P, SEQ, DIM, scale,
                                           MODE_EXP, 1, PS, nullptr, nullptr, nullptr, nullptr,
                                           (size_t)SEQ * DIM, (size_t)SEQ * DIM, (size_t)SEQ * SEQ,
                                           CTR + 1, 16 * 16 * NB, 16, 16);

    // 5) inv row sums
    rowsum_inv<<<MTOT / 256, 256>>>(PS, INV, MTOT);

    // 6) ctx = (expP * V) * inv; tiles 8 x 16 x 4
    gemm_nt_mma<<<NPERS, 256, GEMM_SMEM>>>(P, Vt, nullptr, C, DIM, SEQ, 1.f,
                                           MODE_NORM, 1, INV, nullptr, nullptr, nullptr, nullptr,
                                           (size_t)SEQ * SEQ, (size_t)SEQ * DIM, (size_t)SEQ * DIM,
                                           CTR + 2, 8 * 16 * NB, 8, 16);

    // 7) out = ctx * Wo + bo (fp32 out); tiles 8 x 64
    gemm_nt_mma<<<NPERS, 256, GEMM_SMEM>>>(C, Wt + 3 * (size_t)DIM * DIM, bo, out,
                                           DIM, DIM, 1.f, MODE_PLAIN, 0, nullptr,
                                           nullptr, nullptr, nullptr, nullptr, 0, 0, 0,
                                           CTR + 3, 8 * 64, 8, 64);
}

// round 17
// speedup vs baseline: 1.2847x; 1.2847x over previous
#include <cuda_runtime.h>
#include <cuda_fp16.h>
#include <cstdint>

// Problem constants
#define NB   4
#define SEQ  2048
#define DIM  1024
#define MTOT (NB * SEQ)   // 8192

// GEMM tiling (fp16 operands), 2 CTAs/SM  (measured-optimal config)
#define BM 128
#define BN 128
#define BK 64                            // 64 halves = 128 B per row slab
#define ASTAGE (BM * BK * 2)             // 16384 B
#define BSTAGE (BN * BK * 2)             // 16384 B
#define STAGEB (ASTAGE + BSTAGE)         // 32768 B
#define GEMM_SMEM (3 * STAGEB)           // 98304 B (3 stages; covers 128*129*4 staging)

// Epilogue modes
#define MODE_PLAIN 0   // C = alpha*acc + bias            (outHalf ? half : float)
#define MODE_EXP   1   // C = h(exp(alpha*acc)); aux = partial row sums [rows][64]
#define MODE_NORM  2   // C = h(acc * aux[row])           (aux = inv row sums)
#define MODE_TRANSV 3  // C^T write (Vt half): bias, per-batch [DIM][SEQ]
#define MODE_QKV   4   // fused QKV: seg 0 -> Q plain, seg 1 -> K plain, seg 2 -> Vt transposed

// ---------------- scratch (__device__ globals; no allocation allowed) ------
__device__ __half g_X [(size_t)MTOT * DIM];
__device__ __half g_Q [(size_t)MTOT * DIM];
__device__ __half g_K [(size_t)MTOT * DIM];
__device__ __half g_Vt[(size_t)MTOT * DIM];
__device__ __half g_P [(size_t)NB * SEQ * SEQ];
__device__ __half g_C [(size_t)MTOT * DIM];
__device__ __half g_Wt[(size_t)4 * DIM * DIM];
__device__ float  g_ps[(size_t)MTOT * 64];
__device__ float  g_inv[(size_t)MTOT];

// ---------------- helpers ---------------------------------------------------
__device__ __forceinline__ uint32_t smem_u32(const void* p) {
    uint32_t a;
    asm("{ .reg .u64 t; cvta.to.shared.u64 t, %1; cvt.u32.u64 %0, t; }" : "=r"(a) : "l"(p));
    return a;
}

__device__ __forceinline__ uint32_t h2pack(float a, float b) {
    __half2 h = __floats2half2_rn(a, b);
    return *(uint32_t*)&h;
}

#define CP_ASYNC16(dst, src) \
    asm volatile("cp.async.cg.shared.global [%0], [%1], 16;" :: "r"(dst), "l"(src) : "memory")
#define CP_COMMIT() asm volatile("cp.async.commit_group;" ::: "memory")
#define CP_WAIT1()  asm volatile("cp.async.wait_group 1;" ::: "memory")

__device__ __forceinline__ void ldsm4(uint32_t* r, uint32_t addr) {
    asm volatile("ldmatrix.sync.aligned.m8n8.x4.shared.b16 {%0,%1,%2,%3}, [%4];"
                 : "=r"(r[0]), "=r"(r[1]), "=r"(r[2]), "=r"(r[3]) : "r"(addr));
}

// m16n8k16 fp16, fp32 accumulate (the rate-limiting but fully-harvested form)
__device__ __forceinline__ void mma16(float* c, const uint32_t* a, const uint32_t* b) {
    asm volatile(
        "mma.sync.aligned.m16n8k16.row.col.f32.f16.f16.f32 "
        "{%0,%1,%2,%3}, {%4,%5,%6,%7}, {%8,%9}, {%0,%1,%2,%3};"
        : "+f"(c[0]), "+f"(c[1]), "+f"(c[2]), "+f"(c[3])
        : "r"(a[0]), "r"(a[1]), "r"(a[2]), "r"(a[3]),
          "r"(b[0]), "r"(b[1]));
}

// ---------------- NT GEMM (mma.sync fp16 + ldmatrix + cp.async) -------------
// acc[M,N] = A[M,K] * B[N,K]^T ; epilogue per mode.
// A, B K-major fp16. M%128==0, N%128==0, K%64==0 (K>=192).
// 256 threads, 8 warps (2 m x 4 n), warp tile 64x32, 3-stage cp.async,
// 2 CTAs resident per SM.
__global__ __launch_bounds__(256, 2)
void gemm_nt_mma(const __half* __restrict__ A, const __half* __restrict__ B,
                 const float* __restrict__ bias, void* __restrict__ Cv,
                 int N, int K, float alpha, int mode, int outHalf,
                 float* __restrict__ aux,
                 const float* __restrict__ bias2, const float* __restrict__ bias3,
                 void* __restrict__ Cv2, void* __restrict__ Cv3,
                 size_t strA, size_t strB, size_t strC)
{
    extern __shared__ char smem[];
    const uint32_t sbase = smem_u32(smem);

    A += (size_t)blockIdx.z * strA;
    B += (size_t)blockIdx.z * strB;
    __half* Ch = (__half*)Cv + (size_t)blockIdx.z * strC;
    float*  Cf = (float*)Cv  + (size_t)blockIdx.z * strC;

    const int tid  = threadIdx.x;
    const int lane = tid & 31;
    const int wid  = tid >> 5;
    const int wm   = wid & 1;          // 2 warps along M (64 rows each)
    const int wn   = wid >> 1;         // 4 warps along N (32 cols each)
    const int m0   = blockIdx.y * BM;
    const int n0   = blockIdx.x * BN;

    float acc[4][4][4];
#pragma unroll
    for (int i = 0; i < 4; i++)
#pragma unroll
        for (int j = 0; j < 4; j++)
#pragma unroll
            for (int r = 0; r < 4; r++) acc[i][j][r] = 0.f;

    // loader lane mapping: 16B chunk lc (8 halves) of row lr (+p*32)
    const int lr = tid >> 3;           // 0..31
    const int lc = tid & 7;            // 0..7

    // ldmatrix octet mapping (same for A and B)
    const int lrow = (lane & 7) + ((lane >> 3) & 1) * 8;
    const int lcol = ((lane >> 4) & 1) * 16;
    const uint32_t xmask = (uint32_t)((lane & 7) << 4);   // swizzle XOR (row&7)

    uint32_t abase[4], bbase[2];
#pragma unroll
    for (int mi = 0; mi < 4; mi++)
        abase[mi] = (uint32_t)((wm * 64 + mi * 16 + lrow) * 128 + lcol);
#pragma unroll
    for (int q = 0; q < 2; q++)
        bbase[q] = (uint32_t)((wn * 32 + q * 16 + lrow) * 128 + lcol);

    auto loadStage = [&](int i, int s) {
        const uint32_t baseA = sbase + (uint32_t)s * STAGEB;
        const uint32_t baseB = baseA + ASTAGE;
        const __half* Ag = A + (size_t)m0 * K + (size_t)i * BK + lc * 8;
        const __half* Bg = B + (size_t)n0 * K + (size_t)i * BK + lc * 8;
#pragma unroll
        for (int p = 0; p < 4; p++) {
            const int r = p * 32 + lr;
            CP_ASYNC16(baseA + (uint32_t)(r * 128 + ((lc ^ (r & 7)) * 16)),
                       (const void*)(Ag + (size_t)r * K));
        }
#pragma unroll
        for (int p = 0; p < 4; p++) {
            const int r = p * 32 + lr;
            CP_ASYNC16(baseB + (uint32_t)(r * 128 + ((lc ^ (r & 7)) * 16)),
                       (const void*)(Bg + (size_t)r * K));
        }
    };

    const int nIter = K / BK;
    loadStage(0, 0); CP_COMMIT();
    loadStage(1, 1); CP_COMMIT();

    int s = 0;
    for (int i = 0; i < nIter; i++) {
        CP_WAIT1();
        __syncthreads();

        const uint32_t aS = sbase + (uint32_t)s * STAGEB;
        const uint32_t bS = aS + ASTAGE;
#pragma unroll
        for (int kk = 0; kk < 4; kk++) {        // kk covers 16 halves = 32 B
            uint32_t a[4][4];
            uint32_t b[4][2];
#pragma unroll
            for (int mi = 0; mi < 4; mi++)
                ldsm4(a[mi], aS + ((abase[mi] + kk * 32) ^ xmask));
#pragma unroll
            for (int q = 0; q < 2; q++) {
                uint32_t r[4];
                ldsm4(r, bS + ((bbase[q] + kk * 32) ^ xmask));
                b[2 * q][0]     = r[0]; b[2 * q][1]     = r[2];
                b[2 * q + 1][0] = r[1]; b[2 * q + 1][1] = r[3];
            }
#pragma unroll
            for (int mi = 0; mi < 4; mi++)
#pragma unroll
                for (int ni = 0; ni < 4; ni++)
                    mma16(acc[mi][ni], a[mi], b[ni]);
        }

        if (i + 2 < nIter) {
            int s2 = s + 2; if (s2 >= 3) s2 -= 3;
            loadStage(i + 2, s2);
        }
        CP_COMMIT();
        s++; if (s == 3) s = 0;
    }

    // ---- epilogues ----
    const int g  = lane >> 2;
    const int tg = lane & 3;
    const int growBase = blockIdx.z * (gridDim.y * BM) + m0 + wm * 64;

    if (mode == MODE_QKV) {
        const int seg = n0 >> 10;          // 0:Q  1:K  2:Vt (N segments of 1024)
        if (seg < 2) {
            __half* dstb = (seg == 0) ? Ch : (__half*)Cv2;
            const float* bb = (seg == 0) ? bias : bias2;
#pragma unroll
            for (int mi = 0; mi < 4; mi++) {
                const int mrow = m0 + wm * 64 + mi * 16 + g;
#pragma unroll
                for (int ni = 0; ni < 4; ni++) {
                    const int nc  = n0 + wn * 32 + ni * 8 + 2 * tg;
                    const int ncl = nc & 1023;
                    float b0 = __ldg(bb + ncl), b1 = __ldg(bb + ncl + 1);
                    *(uint32_t*)&dstb[(size_t)mrow * DIM + ncl] =
                        h2pack(acc[mi][ni][0] + b0, acc[mi][ni][1] + b1);
                    *(uint32_t*)&dstb[(size_t)(mrow + 8) * DIM + ncl] =
                        h2pack(acc[mi][ni][2] + b0, acc[mi][ni][3] + b1);
                }
            }
        } else {
            // Vt transposed write: per-batch [DIM][SEQ], bias3, out Cv3
            __syncthreads();
            float* sf = (float*)smem;
#pragma unroll
            for (int mi = 0; mi < 4; mi++) {
                const int mr = wm * 64 + mi * 16 + g;
#pragma unroll
                for (int ni = 0; ni < 4; ni++) {
                    const int ncl = wn * 32 + ni * 8 + 2 * tg;
                    const int nbi = (n0 & 1023) + ncl;
                    float b0 = __ldg(bias3 + nbi), b1 = __ldg(bias3 + nbi + 1);
                    sf[(ncl)     * 129 + mr]     = acc[mi][ni][0] + b0;
                    sf[(ncl + 1) * 129 + mr]     = acc[mi][ni][1] + b1;
                    sf[(ncl)     * 129 + mr + 8] = acc[mi][ni][2] + b0;
                    sf[(ncl + 1) * 129 + mr + 8] = acc[mi][ni][3] + b1;
                }
            }
            __syncthreads();
            const int b  = m0 >> 11;           // batch (SEQ = 2048 rows)
            const int s0 = m0 & 2047;
            const int col = tid & 127;
            const int rh  = (tid >> 7) * 64;
            __half* dst = (__half*)Cv3 + (size_t)b * DIM * SEQ
                        + (size_t)((n0 & 1023) + col) * SEQ + s0 + rh;
            const float* src = sf + (size_t)col * 129 + rh;
#pragma unroll
            for (int m4 = 0; m4 < 64; m4 += 4) {
                uint2 v;
                v.x = h2pack(src[m4],     src[m4 + 1]);
                v.y = h2pack(src[m4 + 2], src[m4 + 3]);
                *(uint2*)(dst + m4) = v;
            }
        }
        return;
    }

    if (mode == MODE_TRANSV) {
        __syncthreads();
        float* sf = (float*)smem;
#pragma unroll
        for (int mi = 0; mi < 4; mi++) {
            const int mr = wm * 64 + mi * 16 + g;
#pragma unroll
            for (int ni = 0; ni < 4; ni++) {
                const int ncl = wn * 32 + ni * 8 + 2 * tg;
                const int ncg = n0 + ncl;
                float b0 = __ldg(bias + ncg), b1 = __ldg(bias + ncg + 1);
                sf[(ncl)     * 129 + mr]     = acc[mi][ni][0] + b0;
                sf[(ncl + 1) * 129 + mr]     = acc[mi][ni][1] + b1;
                sf[(ncl)     * 129 + mr + 8] = acc[mi][ni][2] + b0;
                sf[(ncl + 1) * 129 + mr + 8] = acc[mi][ni][3] + b1;
            }
        }
        __syncthreads();
        const int b  = m0 >> 11;
        const int s0 = m0 & 2047;
        const int col = tid & 127;
        const int rh  = (tid >> 7) * 64;
        __half* dst = Ch + (size_t)b * DIM * SEQ + (size_t)(n0 + col) * SEQ + s0 + rh;
        const float* src = sf + (size_t)col * 129 + rh;
#pragma unroll
        for (int m4 = 0; m4 < 64; m4 += 4) {
            uint2 v;
            v.x = h2pack(src[m4],     src[m4 + 1]);
            v.y = h2pack(src[m4 + 2], src[m4 + 3]);
            *(uint2*)(dst + m4) = v;
        }
        return;
    }

    if (mode == MODE_EXP) {
        float rs[4][2];
#pragma unroll
        for (int mi = 0; mi < 4; mi++) { rs[mi][0] = 0.f; rs[mi][1] = 0.f; }
#pragma unroll
        for (int mi = 0; mi < 4; mi++) {
            const int mrow = m0 + wm * 64 + mi * 16 + g;
#pragma unroll
            for (int ni = 0; ni < 4; ni++) {
                const int nc = n0 + wn * 32 + ni * 8 + 2 * tg;
                __half2 h0 = __floats2half2_rn(__expf(acc[mi][ni][0] * alpha),
                                               __expf(acc[mi][ni][1] * alpha));
                __half2 h1 = __floats2half2_rn(__expf(acc[mi][ni][2] * alpha),
                                               __expf(acc[mi][ni][3] * alpha));
                float2 f0 = __half22float2(h0);
                float2 f1 = __half22float2(h1);
                rs[mi][0] += f0.x + f0.y;
                rs[mi][1] += f1.x + f1.y;
                *(__half2*)&Ch[(size_t)mrow * N + nc]       = h0;
                *(__half2*)&Ch[(size_t)(mrow + 8) * N + nc] = h1;
            }
        }
        const int slot = blockIdx.x * 4 + wn;    // gridDim.x = 16 -> slots 0..63
#pragma unroll
        for (int mi = 0; mi < 4; mi++) {
#pragma unroll
            for (int h = 0; h < 2; h++) {
                float v = rs[mi][h];
                v += __shfl_xor_sync(0xffffffffu, v, 1);
                v += __shfl_xor_sync(0xffffffffu, v, 2);
                if (tg == 0) {
                    const int grow = growBase + mi * 16 + g + h * 8;
                    aux[(size_t)grow * 64 + slot] = v;
                }
            }
        }
        return;
    }

    // MODE_PLAIN / MODE_NORM
#pragma unroll
    for (int mi = 0; mi < 4; mi++) {
        const int mrow = m0 + wm * 64 + mi * 16 + g;
        float inv0 = 1.f, inv1 = 1.f;
        if (mode == MODE_NORM) {
            const int grow = growBase + mi * 16 + g;
            inv0 = __ldg(aux + grow);
            inv1 = __ldg(aux + grow + 8);
        }
#pragma unroll
        for (int ni = 0; ni < 4; ni++) {
            const int nc = n0 + wn * 32 + ni * 8 + 2 * tg;
            float b0 = 0.f, b1 = 0.f;
            if (bias) { b0 = __ldg(bias + nc); b1 = __ldg(bias + nc + 1); }
            float2 r0, r1;
            if (mode == MODE_NORM) {
                r0 = make_float2(acc[mi][ni][0] * inv0, acc[mi][ni][1] * inv0);
                r1 = make_float2(acc[mi][ni][2] * inv1, acc[mi][ni][3] * inv1);
            } else {
                r0 = make_float2(acc[mi][ni][0] * alpha + b0, acc[mi][ni][1] * alpha + b1);
                r1 = make_float2(acc[mi][ni][2] * alpha + b0, acc[mi][ni][3] * alpha + b1);
            }
            if (outHalf) {
                *(uint32_t*)&Ch[(size_t)mrow * N + nc]       = h2pack(r0.x, r0.y);
                *(uint32_t*)&Ch[(size_t)(mrow + 8) * N + nc] = h2pack(r1.x, r1.y);
            } else {
                *(float2*)&Cf[(size_t)mrow * N + nc]       = r0;
                *(float2*)&Cf[(size_t)(mrow + 8) * N + nc] = r1;
            }
        }
    }
}

// ---------------- aux kernels ----------------------------------------------

// fp32 -> fp16 copy (prepares x for the projection GEMMs)
__global__ __launch_bounds__(256)
void half_copy4(const float4* __restrict__ in, uint2* __restrict__ out, int n4)
{
    int i = blockIdx.x * 256 + threadIdx.x;
    if (i < n4) {
        float4 v = in[i];
        uint2 o;
        o.x = h2pack(v.x, v.y);
        o.y = h2pack(v.z, v.w);
        out[i] = o;
    }
}

// all 4 weight transposes in one launch: out[z][C,R] = half(W_z[R,C]^T)
__global__ __launch_bounds__(256)
void transpose4w(const float* __restrict__ W0, const float* __restrict__ W1,
                 const float* __restrict__ W2, const float* __restrict__ W3,
                 __half* __restrict__ out)
{
    __shared__ float t[32][33];
    const float* in = (blockIdx.z == 0) ? W0 : (blockIdx.z == 1) ? W1
                    : (blockIdx.z == 2) ? W2 : W3;
    __half* dst = out + (size_t)blockIdx.z * DIM * DIM;
    const int x  = blockIdx.x * 32 + threadIdx.x;
    const int y0 = blockIdx.y * 32;
#pragma unroll
    for (int j = threadIdx.y; j < 32; j += 8)
        t[j][threadIdx.x] = in[(size_t)(y0 + j) * DIM + x];
    __syncthreads();
    const int ox  = y0 + threadIdx.x;
    const int oy0 = blockIdx.x * 32;
#pragma unroll
    for (int j = threadIdx.y; j < 32; j += 8)
        dst[(size_t)(oy0 + j) * DIM + ox] = __float2half_rn(t[threadIdx.x][j]);
}

// inv[r] = 1 / sum(partial[r][0..63])
__global__ __launch_bounds__(256)
void rowsum_inv(const float* __restrict__ partial, float* __restrict__ inv, int rows)
{
    int r = blockIdx.x * 256 + threadIdx.x;
    if (r < rows) {
        const float4* p = (const float4*)(partial + (size_t)r * 64);
        float s = 0.f;
#pragma unroll
        for (int i = 0; i < 16; i++) {
            float4 v = p[i];
            s += (v.x + v.y) + (v.z + v.w);
        }
        inv[r] = 1.0f / s;
    }
}

// ---------------- launch ----------------------------------------------------
extern "C" void kernel_launch(void* const* d_in, const int* in_sizes, int n_in,
                              void* d_out, int out_size)
{
    const float* x  = (const float*)d_in[0];
    const float* Wq = (const float*)d_in[1];
    const float* bq = (const float*)d_in[2];
    const float* Wk = (const float*)d_in[3];
    const float* bk = (const float*)d_in[4];
    const float* Wv = (const float*)d_in[5];
    const float* bv = (const float*)d_in[6];
    const float* Wo = (const float*)d_in[7];
    const float* bo = (const float*)d_in[8];
    float* out = (float*)d_out;

    __half *X, *Q, *K, *Vt, *P, *C, *Wt;
    float *PS, *INV;
    cudaGetSymbolAddress((void**)&X,   g_X);
    cudaGetSymbolAddress((void**)&Q,   g_Q);
    cudaGetSymbolAddress((void**)&K,   g_K);
    cudaGetSymbolAddress((void**)&Vt,  g_Vt);
    cudaGetSymbolAddress((void**)&P,   g_P);
    cudaGetSymbolAddress((void**)&C,   g_C);
    cudaGetSymbolAddress((void**)&Wt,  g_Wt);
    cudaGetSymbolAddress((void**)&PS,  g_ps);
    cudaGetSymbolAddress((void**)&INV, g_inv);

    cudaFuncSetAttribute(gemm_nt_mma, cudaFuncAttributeMaxDynamicSharedMemorySize, GEMM_SMEM);

    const float scale = 1.0f / 32.0f;   // 1/sqrt(1024)

    // 1) fp16 x
    half_copy4<<<(MTOT * DIM / 4 + 255) / 256, 256>>>((const float4*)x, (uint2*)X, MTOT * DIM / 4);

    // 2) all weight transposes (one launch); Wt = [Wq^T | Wk^T | Wv^T | Wo^T]
    transpose4w<<<dim3(DIM / 32, DIM / 32, 4), dim3(32, 8)>>>(Wq, Wk, Wv, Wo, Wt);

    dim3 g_qkv(3 * DIM / BN, MTOT / BM, 1);  // 24 x 64 = 1536 CTAs, one launch
    dim3 g_proj(DIM / BN, MTOT / BM, 1);     // 8 x 64
    dim3 g_sc(SEQ / BN, SEQ / BM, NB);       // 16 x 16 x 4
    dim3 g_ctx(DIM / BN, SEQ / BM, NB);      // 8 x 16 x 4

    // 3) fused QKV projection: seg0 -> Q (half), seg1 -> K (half), seg2 -> Vt (transposed half)
    gemm_nt_mma<<<g_qkv, 256, GEMM_SMEM>>>(X, Wt, bq, Q,
                                           DIM, DIM, 1.f, MODE_QKV, 1, nullptr,
                                           bk, bv, K, Vt, 0, 0, 0);

    // 4) expP = exp(scale * Q K^T) (half), partial row sums
    gemm_nt_mma<<<g_sc, 256, GEMM_SMEM>>>(Q, K, nullptr, P, SEQ, DIM, scale,
                                          MODE_EXP, 1, PS, nullptr, nullptr, nullptr, nullptr,
                                          (size_t)SEQ * DIM, (size_t)SEQ * DIM, (size_t)SEQ * SEQ);

    // 5) inv row sums
    rowsum_inv<<<MTOT / 256, 256>>>(PS, INV, MTOT);

    // 6) ctx = (expP * V) * inv   (A=P [S,S], B=Vt [D,S]) -> half
    gemm_nt_mma<<<g_ctx, 256, GEMM_SMEM>>>(P, Vt, nullptr, C, DIM, SEQ, 1.f,
                                           MODE_NORM, 1, INV, nullptr, nullptr, nullptr, nullptr,
                                           (size_t)SEQ * SEQ, (size_t)SEQ * DIM, (size_t)SEQ * DIM);

    // 7) out = ctx * Wo + bo (fp32 out)
    gemm_nt_mma<<<g_proj, 256, GEMM_SMEM>>>(C, Wt + 3 * (size_t)DIM * DIM, bo, out,
                                            DIM, DIM, 1.f, MODE_PLAIN, 0, nullptr,
                                            nullptr, nullptr, nullptr, nullptr, 0, 0, 0);
}